// round 13
// baseline (speedup 1.0000x reference)
#include <cuda_runtime.h>
#include <cuda_fp16.h>
#include <math.h>
#include <stdint.h>

#define B_DIM   8
#define HW_DIM  3136
#define C_DIM   256
#define NROWS   (B_DIM * HW_DIM)        // 25088
#define JT      64                      // j tile
#define NJT     (HW_DIM / JT)           // 49

// fused smem (bytes). X rows pitch 36 u4 (LDS.128-conflict-free, proven),
// T rows pitch 10 u4 (=40 words -> conflict-free 2-phase LDS.64 in ph2).
#define XP      36
#define TPW     10                      // T row pitch in u4 (160B)
#define SM_XI   0                       // 64*36*16  = 36864
#define SM_XJ0  36864
#define SM_XJ1  73728
#define SM_TT0  110592                  // 256*10*16 = 40960
#define SM_TT1  151552
#define SM_TOT  192512

// transform_mma smem: Wt 256 rows x 36 u4, X/staging 64x36 u4
#define TM_WT   0
#define TM_XT   147456
#define TM_TOT  184320

// device-global scratch (fp16)
__device__ __align__(16) unsigned short g_xn[(size_t)NROWS * C_DIM];          // xn [row][c]
__device__ __align__(16) unsigned short g_xh[(size_t)NROWS * C_DIM];          // raw x fp16
__device__ __align__(16) unsigned short g_wt[(size_t)C_DIM * C_DIM];          // W^T [c][k]
// t transposed [b][c][hw], hw PERMUTED within 16-groups (pi below)
__device__ __align__(16) unsigned short g_tt[(size_t)B_DIM * C_DIM * HW_DIM];

__device__ __forceinline__ uint32_t h2pack(float a, float b) {
    __half2 h = __floats2half2_rn(a, b);
    return *reinterpret_cast<uint32_t*>(&h);
}
__device__ __forceinline__ uint32_t smem_u32(const void* p) {
    uint32_t a;
    asm("{ .reg .u64 t; cvta.to.shared.u64 t, %1; cvt.u32.u64 %0, t; }" : "=r"(a) : "l"(p));
    return a;
}
__device__ __forceinline__ void cp16(uint32_t dst, const void* src) {
    asm volatile("{ .reg .u64 g; cvta.to.global.u64 g, %1;"
                 " cp.async.cg.shared.global [%0], [g], 16; }" :: "r"(dst), "l"(src));
}
#define CP_COMMIT() asm volatile("cp.async.commit_group;" ::: "memory")
#define CP_WAIT0()  asm volatile("cp.async.wait_group 0;" ::: "memory")
#define CP_WAIT1()  asm volatile("cp.async.wait_group 1;" ::: "memory")

__device__ __forceinline__ void mma16(float* d, uint32_t a0, uint32_t a1,
                                      uint32_t a2, uint32_t a3,
                                      uint32_t b0, uint32_t b1) {
    asm volatile(
        "mma.sync.aligned.m16n8k16.row.col.f32.f16.f16.f32 "
        "{%0,%1,%2,%3}, {%4,%5,%6,%7}, {%8,%9}, {%0,%1,%2,%3};"
        : "+f"(d[0]), "+f"(d[1]), "+f"(d[2]), "+f"(d[3])
        : "r"(a0), "r"(a1), "r"(a2), "r"(a3), "r"(b0), "r"(b1));
}

// ---------------------------------------------------------------------------
// Kernel A: L2 normalize -> g_xn (fp16) and raw x -> g_xh (fp16)
// ---------------------------------------------------------------------------
__global__ void norm_kernel(const float* __restrict__ x) {
    int row  = blockIdx.x * 8 + threadIdx.y;
    int lane = threadIdx.x;
    const float4* xr = reinterpret_cast<const float4*>(x) + (size_t)row * (C_DIM / 4);
    float4 v0 = xr[lane];
    float4 v1 = xr[lane + 32];
    float s = v0.x*v0.x + v0.y*v0.y + v0.z*v0.z + v0.w*v0.w
            + v1.x*v1.x + v1.y*v1.y + v1.z*v1.z + v1.w*v1.w;
#pragma unroll
    for (int off = 16; off > 0; off >>= 1) s += __shfl_xor_sync(0xffffffffu, s, off);
    float inv = rsqrtf(fmaxf(s, 1e-12f));
    uint2* oh = reinterpret_cast<uint2*>(g_xh) + (size_t)row * (C_DIM / 4);
    oh[lane]      = make_uint2(h2pack(v0.x, v0.y), h2pack(v0.z, v0.w));
    oh[lane + 32] = make_uint2(h2pack(v1.x, v1.y), h2pack(v1.z, v1.w));
    uint2* o = reinterpret_cast<uint2*>(g_xn) + (size_t)row * (C_DIM / 4);
    o[lane]      = make_uint2(h2pack(v0.x*inv, v0.y*inv), h2pack(v0.z*inv, v0.w*inv));
    o[lane + 32] = make_uint2(h2pack(v1.x*inv, v1.y*inv), h2pack(v1.z*inv, v1.w*inv));
}

// ---------------------------------------------------------------------------
// Kernel A2: W^T -> g_wt[c][k] fp16
// ---------------------------------------------------------------------------
__global__ void wt_kernel(const float* __restrict__ W) {
    int c = blockIdx.x, k = threadIdx.x;
    g_wt[(size_t)c * C_DIM + k] = __half_as_ushort(__float2half_rn(W[(size_t)k * C_DIM + c]));
}

// ---------------------------------------------------------------------------
// Kernel B: t = x @ W fp16 HMMA; stored transposed [b][c][hw] with hw
// permuted within 16-groups:  pi(j) = ((j&7)>>1)*4 + (j&1) + ((j>>3)<<1)
// so that ph2 B-fragments are single contiguous LDS.64 loads.
// ---------------------------------------------------------------------------
__global__ __launch_bounds__(256)
void transform_mma() {
    extern __shared__ char smem[];
    uint32_t sbase = smem_u32(smem);
    const uint4* Wt4 = reinterpret_cast<const uint4*>(smem + TM_WT);
    const uint4* X4  = reinterpret_cast<const uint4*>(smem + TM_XT);
    __half*      stg = reinterpret_cast<__half*>(smem + TM_XT);

    int row0 = blockIdx.x * 64;
    int tid = threadIdx.x, w = tid >> 5, lane = tid & 31;
    int gid = lane >> 2, tig = lane & 3;
    int wr = w & 1, wn = w >> 1;

#pragma unroll
    for (int q = 0; q < 32; q++) {
        int idx = tid + q * 256, r = idx >> 5, c4 = idx & 31;
        cp16(sbase + TM_WT + (uint32_t)(r * XP + c4) * 16,
             g_wt + (size_t)r * C_DIM + c4 * 8);
    }
#pragma unroll
    for (int q = 0; q < 8; q++) {
        int idx = tid + q * 256, r = idx >> 5, c4 = idx & 31;
        cp16(sbase + TM_XT + (uint32_t)(r * XP + c4) * 16,
             g_xh + (size_t)(row0 + r) * C_DIM + c4 * 8);
    }
    CP_COMMIT(); CP_WAIT0();
    __syncthreads();

    float yacc[2][8][4];
#pragma unroll
    for (int mb = 0; mb < 2; mb++)
#pragma unroll
        for (int nt = 0; nt < 8; nt++)
#pragma unroll
            for (int q = 0; q < 4; q++) yacc[mb][nt][q] = 0.f;

#pragma unroll
    for (int kc = 0; kc < 8; kc++) {
        uint4 Ag[2], Ag8[2];
#pragma unroll
        for (int mb = 0; mb < 2; mb++) {
            int r1 = 32 * wr + 16 * mb + gid;
            Ag[mb]  = X4[r1 * XP + 4 * kc + tig];
            Ag8[mb] = X4[(r1 + 8) * XP + 4 * kc + tig];
        }
#pragma unroll
        for (int nt = 0; nt < 8; nt++) {
            int c = 64 * wn + 8 * nt + gid;
            uint4 Bv = Wt4[c * XP + 4 * kc + tig];
            const uint32_t* bn = reinterpret_cast<const uint32_t*>(&Bv);
#pragma unroll
            for (int ss = 0; ss < 2; ss++)
#pragma unroll
                for (int mb = 0; mb < 2; mb++) {
                    const uint32_t* ag  = reinterpret_cast<const uint32_t*>(&Ag[mb]);
                    const uint32_t* ag8 = reinterpret_cast<const uint32_t*>(&Ag8[mb]);
                    mma16(yacc[mb][nt], ag[2*ss], ag8[2*ss], ag[2*ss+1], ag8[2*ss+1],
                          bn[2*ss], bn[2*ss+1]);
                }
        }
    }
    __syncthreads();

    // stage transposed with hw-permutation within 16-groups
    int pg  = (gid >> 1) * 4 + (gid & 1);    // pi(gid), gid<8
#pragma unroll
    for (int mb = 0; mb < 2; mb++)
#pragma unroll
        for (int nt = 0; nt < 8; nt++) {
            int grp = 32 * wr + 16 * mb;     // 16-group base
            int c   = 64 * wn + 8 * nt + 2 * tig;
            stg[c * 72 + grp + pg]           = __float2half_rn(yacc[mb][nt][0]);
            stg[(c + 1) * 72 + grp + pg]     = __float2half_rn(yacc[mb][nt][1]);
            stg[c * 72 + grp + pg + 2]       = __float2half_rn(yacc[mb][nt][2]);
            stg[(c + 1) * 72 + grp + pg + 2] = __float2half_rn(yacc[mb][nt][3]);
        }
    __syncthreads();

    int bb = row0 / HW_DIM, hw0 = row0 - bb * HW_DIM;
#pragma unroll
    for (int p = 0; p < 4; p++) {
        int c = p * 64 + (tid >> 2), ch = tid & 3;
        uint4 v  = *reinterpret_cast<const uint4*>(&stg[c * 72 + ch * 16]);
        uint4 v2 = *reinterpret_cast<const uint4*>(&stg[c * 72 + ch * 16 + 8]);
        *reinterpret_cast<uint4*>(
            &g_tt[((size_t)bb * C_DIM + c) * HW_DIM + hw0 + ch * 16]) = v;
        *reinterpret_cast<uint4*>(
            &g_tt[((size_t)bb * C_DIM + c) * HW_DIM + hw0 + ch * 16 + 8]) = v2;
    }
}

// ---------------------------------------------------------------------------
// Kernel C: fused pass with FA-style register reuse.
//   512 thr, 16 warps: wm = w&3 (16-row group), wk = (w>>2)&1 (32-j k-slice),
//   wn2 = w>>3 (128-col Y half). ph1: warp computes S(16x32) for its k-slice
//   (duplicated across wn2 twins). relu^2 in regs -> A-fragments directly.
//   ph2: Y-partial(16x128) over the 32-k slice; k-halves reduced in epilogue.
// ---------------------------------------------------------------------------
__global__ __launch_bounds__(512)
void ppm_fused(float* __restrict__ y) {
    extern __shared__ char smem[];
    uint32_t sbase = smem_u32(smem);
    const uint4* Xi4 = reinterpret_cast<const uint4*>(smem + SM_XI);

    int b  = blockIdx.y;
    int i0 = blockIdx.x * JT;
    const unsigned short* Xg = g_xn + (size_t)b * HW_DIM * C_DIM;
    const unsigned short* Tg = g_tt + (size_t)b * C_DIM * HW_DIM;

    int tid = threadIdx.x, w = tid >> 5, lane = tid & 31;
    int gid = lane >> 2, tig = lane & 3;
    int wm = w & 3, wk = (w >> 2) & 1, wn2 = w >> 3;

    const uint32_t xjOff[2] = {SM_XJ0, SM_XJ1};
    const uint32_t ttOff[2] = {SM_TT0, SM_TT1};

    auto loadX = [&](int r0, uint32_t dstb) {
#pragma unroll
        for (int q = 0; q < 4; q++) {
            int idx = tid + q * 512, r = idx >> 5, c4 = idx & 31;
            cp16(sbase + dstb + (uint32_t)(r * XP + c4) * 16,
                 Xg + (size_t)(r0 + r) * C_DIM + c4 * 8);
        }
    };
    auto loadT = [&](int j0, uint32_t dstb) {
#pragma unroll
        for (int q = 0; q < 4; q++) {
            int idx = tid + q * 512, c = idx >> 3, k4 = idx & 7;
            cp16(sbase + dstb + (uint32_t)(c * TPW + k4) * 16,
                 Tg + (size_t)c * HW_DIM + j0 + k4 * 8);
        }
    };

    loadX(i0, SM_XI);
    loadX(0, SM_XJ0);
    loadT(0, SM_TT0);
    CP_COMMIT();
    loadX(JT, SM_XJ1);
    loadT(JT, SM_TT1);
    CP_COMMIT();

    float yacc[16][4];
#pragma unroll
    for (int nt = 0; nt < 16; nt++)
#pragma unroll
        for (int q = 0; q < 4; q++) yacc[nt][q] = 0.f;

    int r1a = 16 * wm + gid;

    for (int j = 0; j < NJT; j++) {
        int s = j & 1;
        if (j >= NJT - 2) CP_WAIT0(); else CP_WAIT1();
        __syncthreads();
        const uint4*     Xj4 = reinterpret_cast<const uint4*>(smem + xjOff[s]);
        const uint32_t*  T32 = reinterpret_cast<const uint32_t*>(smem + ttOff[s]);

        // ---- phase 1: S(16 rows x 32 cols of this warp's k-slice) = Xi @ Xj^T
        float sacc[4][4] = {};
#pragma unroll
        for (int kc = 0; kc < 8; kc++) {
            uint4 Ag  = Xi4[r1a * XP + 4 * kc + tig];
            uint4 Ag8 = Xi4[(r1a + 8) * XP + 4 * kc + tig];
            uint4 Bn[4];
#pragma unroll
            for (int nb = 0; nb < 4; nb++) {
                int n1 = 32 * wk + 8 * nb + gid;
                Bn[nb] = Xj4[n1 * XP + 4 * kc + tig];
            }
            const uint32_t* ag  = reinterpret_cast<const uint32_t*>(&Ag);
            const uint32_t* ag8 = reinterpret_cast<const uint32_t*>(&Ag8);
#pragma unroll
            for (int ss = 0; ss < 2; ss++)
#pragma unroll
                for (int nb = 0; nb < 4; nb++) {
                    const uint32_t* bn = reinterpret_cast<const uint32_t*>(&Bn[nb]);
                    mma16(sacc[nb], ag[2*ss], ag8[2*ss], ag[2*ss+1], ag8[2*ss+1],
                          bn[2*ss], bn[2*ss+1]);
                }
        }

        // ---- relu^2 in regs -> ph2 A-fragments (C-frag == A-frag layout)
        uint32_t afr[2][4];
#pragma unroll
        for (int kb = 0; kb < 2; kb++) {
            float* s0 = sacc[2 * kb];
            float* s1 = sacc[2 * kb + 1];
            float u0 = fmaxf(s0[0], 0.f), u1 = fmaxf(s0[1], 0.f);
            float u2 = fmaxf(s0[2], 0.f), u3 = fmaxf(s0[3], 0.f);
            float v0 = fmaxf(s1[0], 0.f), v1 = fmaxf(s1[1], 0.f);
            float v2 = fmaxf(s1[2], 0.f), v3 = fmaxf(s1[3], 0.f);
            afr[kb][0] = h2pack(u0 * u0, u1 * u1);   // row gid,   k 2tig..+1
            afr[kb][1] = h2pack(u2 * u2, u3 * u3);   // row gid+8, k 2tig..+1
            afr[kb][2] = h2pack(v0 * v0, v1 * v1);   // row gid,   k 2tig+8..+9
            afr[kb][3] = h2pack(v2 * v2, v3 * v3);   // row gid+8, k 2tig+8..+9
        }

        // ---- phase 2: Y-partial(16x128) += relu(S)^2 @ T over this k-slice
#pragma unroll
        for (int kb = 0; kb < 2; kb++) {
            int kwb = 16 * wk + 8 * kb + 2 * tig;    // word base in permuted T row
#pragma unroll
            for (int nt = 0; nt < 16; nt++) {
                int c = 128 * wn2 + 8 * nt + gid;
                uint2 bv = *reinterpret_cast<const uint2*>(&T32[c * (TPW * 4) + kwb]);
                mma16(yacc[nt], afr[kb][0], afr[kb][1], afr[kb][2], afr[kb][3],
                      bv.x, bv.y);
            }
        }
        __syncthreads();               // all reads of Xj[s], T[s] done

        if (j + 2 < NJT) {
            loadX((j + 2) * JT, xjOff[s]);
            loadT((j + 2) * JT, ttOff[s]);
            CP_COMMIT();
        }
    }

    // ---- epilogue: reduce wk=0/1 partials via smem (reuse Xj area), write Y
    float* red = reinterpret_cast<float*>(smem + SM_XJ0)
               + (size_t)(wm * 2 + wn2) * (16 * 132);
    if (wk == 1) {
#pragma unroll
        for (int nt = 0; nt < 16; nt++) {
            int col = 8 * nt + 2 * tig;
            *reinterpret_cast<float2*>(&red[gid * 132 + col]) =
                make_float2(yacc[nt][0], yacc[nt][1]);
            *reinterpret_cast<float2*>(&red[(gid + 8) * 132 + col]) =
                make_float2(yacc[nt][2], yacc[nt][3]);
        }
    }
    __syncthreads();
    if (wk == 0) {
        float* Yb = y + ((size_t)b * HW_DIM + i0) * C_DIM;
        int r0 = 16 * wm + gid;
#pragma unroll
        for (int nt = 0; nt < 16; nt++) {
            int col = 8 * nt + 2 * tig;
            float2 p0 = *reinterpret_cast<const float2*>(&red[gid * 132 + col]);
            float2 p1 = *reinterpret_cast<const float2*>(&red[(gid + 8) * 132 + col]);
            int c = 128 * wn2 + col;
            *reinterpret_cast<float2*>(&Yb[(size_t)r0 * C_DIM + c]) =
                make_float2(yacc[nt][0] + p0.x, yacc[nt][1] + p0.y);
            *reinterpret_cast<float2*>(&Yb[(size_t)(r0 + 8) * C_DIM + c]) =
                make_float2(yacc[nt][2] + p1.x, yacc[nt][3] + p1.y);
        }
    }
}

// ---------------------------------------------------------------------------
extern "C" void kernel_launch(void* const* d_in, const int* in_sizes, int n_in,
                              void* d_out, int out_size) {
    const float* x = (const float*)d_in[0];
    const float* W = (const float*)d_in[1];
    float* y = (float*)d_out;
    (void)in_sizes; (void)n_in; (void)out_size;

    norm_kernel<<<NROWS / 8, dim3(32, 8)>>>(x);
    wt_kernel<<<C_DIM, C_DIM>>>(W);

    cudaFuncSetAttribute(transform_mma, cudaFuncAttributeMaxDynamicSharedMemorySize, TM_TOT);
    transform_mma<<<NROWS / 64, 256, TM_TOT>>>();

    cudaFuncSetAttribute(ppm_fused, cudaFuncAttributeMaxDynamicSharedMemorySize, SM_TOT);
    ppm_fused<<<dim3(HW_DIM / JT, B_DIM), 512, SM_TOT>>>(y);
}

// round 14
// speedup vs baseline: 1.2673x; 1.2673x over previous
#include <cuda_runtime.h>
#include <cuda_fp16.h>
#include <math.h>
#include <stdint.h>

#define B_DIM   8
#define HW_DIM  3136
#define C_DIM   256
#define NROWS   (B_DIM * HW_DIM)        // 25088
#define JT      64                      // j tile
#define NJT     (HW_DIM / JT)           // 49

// fused smem (bytes). X rows pitch 36 u4, T rows pitch 12 u4 (conflict-free
// LDS.128 fragment gathers — proven). S ping-pong, pitch 10 u4.
#define XP      36
#define TP      12
#define SPW     10
#define SM_XI   0                       // 64*36*16  = 36864
#define SM_XJ0  36864
#define SM_XJ1  73728
#define SM_TT0  110592                  // 256*12*16 = 49152
#define SM_TT1  159744
#define SM_SS0  208896                  // 64*10*16  = 10240
#define SM_SS1  219136
#define SM_TOT  229376                  // <= 232448 (227KB)

// transform_mma smem: Wt 256 rows x 36 u4, X/staging 64x36 u4
#define TM_WT   0
#define TM_XT   147456
#define TM_TOT  184320

// device-global scratch (fp16)
__device__ __align__(16) unsigned short g_xn[(size_t)NROWS * C_DIM];          // xn [row][c]
__device__ __align__(16) unsigned short g_xh[(size_t)NROWS * C_DIM];          // raw x fp16
__device__ __align__(16) unsigned short g_wt[(size_t)C_DIM * C_DIM];          // W^T [c][k]
__device__ __align__(16) unsigned short g_tt[(size_t)B_DIM * C_DIM * HW_DIM]; // t  [b][c][hw]

__device__ __forceinline__ uint32_t h2pack(float a, float b) {
    __half2 h = __floats2half2_rn(a, b);
    return *reinterpret_cast<uint32_t*>(&h);
}
__device__ __forceinline__ uint32_t smem_u32(const void* p) {
    uint32_t a;
    asm("{ .reg .u64 t; cvta.to.shared.u64 t, %1; cvt.u32.u64 %0, t; }" : "=r"(a) : "l"(p));
    return a;
}
__device__ __forceinline__ void cp16(uint32_t dst, const void* src) {
    asm volatile("{ .reg .u64 g; cvta.to.global.u64 g, %1;"
                 " cp.async.cg.shared.global [%0], [g], 16; }" :: "r"(dst), "l"(src));
}
#define CP_COMMIT() asm volatile("cp.async.commit_group;" ::: "memory")
#define CP_WAIT0()  asm volatile("cp.async.wait_group 0;" ::: "memory")
#define CP_WAIT1()  asm volatile("cp.async.wait_group 1;" ::: "memory")

__device__ __forceinline__ void mma16(float* d, uint32_t a0, uint32_t a1,
                                      uint32_t a2, uint32_t a3,
                                      uint32_t b0, uint32_t b1) {
    asm volatile(
        "mma.sync.aligned.m16n8k16.row.col.f32.f16.f16.f32 "
        "{%0,%1,%2,%3}, {%4,%5,%6,%7}, {%8,%9}, {%0,%1,%2,%3};"
        : "+f"(d[0]), "+f"(d[1]), "+f"(d[2]), "+f"(d[3])
        : "r"(a0), "r"(a1), "r"(a2), "r"(a3), "r"(b0), "r"(b1));
}

// ---------------------------------------------------------------------------
// Kernel A: L2 normalize -> g_xn (fp16) and raw x -> g_xh (fp16)
// ---------------------------------------------------------------------------
__global__ void norm_kernel(const float* __restrict__ x) {
    int row  = blockIdx.x * 8 + threadIdx.y;
    int lane = threadIdx.x;
    const float4* xr = reinterpret_cast<const float4*>(x) + (size_t)row * (C_DIM / 4);
    float4 v0 = xr[lane];
    float4 v1 = xr[lane + 32];
    float s = v0.x*v0.x + v0.y*v0.y + v0.z*v0.z + v0.w*v0.w
            + v1.x*v1.x + v1.y*v1.y + v1.z*v1.z + v1.w*v1.w;
#pragma unroll
    for (int off = 16; off > 0; off >>= 1) s += __shfl_xor_sync(0xffffffffu, s, off);
    float inv = rsqrtf(fmaxf(s, 1e-12f));
    uint2* oh = reinterpret_cast<uint2*>(g_xh) + (size_t)row * (C_DIM / 4);
    oh[lane]      = make_uint2(h2pack(v0.x, v0.y), h2pack(v0.z, v0.w));
    oh[lane + 32] = make_uint2(h2pack(v1.x, v1.y), h2pack(v1.z, v1.w));
    uint2* o = reinterpret_cast<uint2*>(g_xn) + (size_t)row * (C_DIM / 4);
    o[lane]      = make_uint2(h2pack(v0.x*inv, v0.y*inv), h2pack(v0.z*inv, v0.w*inv));
    o[lane + 32] = make_uint2(h2pack(v1.x*inv, v1.y*inv), h2pack(v1.z*inv, v1.w*inv));
}

// ---------------------------------------------------------------------------
// Kernel A2: W^T -> g_wt[c][k] fp16
// ---------------------------------------------------------------------------
__global__ void wt_kernel(const float* __restrict__ W) {
    int c = blockIdx.x, k = threadIdx.x;
    g_wt[(size_t)c * C_DIM + k] = __half_as_ushort(__float2half_rn(W[(size_t)k * C_DIM + c]));
}

// ---------------------------------------------------------------------------
// Kernel B: t = x @ W on fp16 tensor cores; stored transposed: g_tt[b][c][hw]
// (standard layout — NO permutation)
// ---------------------------------------------------------------------------
__global__ __launch_bounds__(256)
void transform_mma() {
    extern __shared__ char smem[];
    uint32_t sbase = smem_u32(smem);
    const uint4* Wt4 = reinterpret_cast<const uint4*>(smem + TM_WT);
    const uint4* X4  = reinterpret_cast<const uint4*>(smem + TM_XT);
    __half*      stg = reinterpret_cast<__half*>(smem + TM_XT);

    int row0 = blockIdx.x * 64;
    int tid = threadIdx.x, w = tid >> 5, lane = tid & 31;
    int gid = lane >> 2, tig = lane & 3;
    int wr = w & 1, wn = w >> 1;

#pragma unroll
    for (int q = 0; q < 32; q++) {
        int idx = tid + q * 256, r = idx >> 5, c4 = idx & 31;
        cp16(sbase + TM_WT + (uint32_t)(r * XP + c4) * 16,
             g_wt + (size_t)r * C_DIM + c4 * 8);
    }
#pragma unroll
    for (int q = 0; q < 8; q++) {
        int idx = tid + q * 256, r = idx >> 5, c4 = idx & 31;
        cp16(sbase + TM_XT + (uint32_t)(r * XP + c4) * 16,
             g_xh + (size_t)(row0 + r) * C_DIM + c4 * 8);
    }
    CP_COMMIT(); CP_WAIT0();
    __syncthreads();

    float yacc[2][8][4];
#pragma unroll
    for (int mb = 0; mb < 2; mb++)
#pragma unroll
        for (int nt = 0; nt < 8; nt++)
#pragma unroll
            for (int q = 0; q < 4; q++) yacc[mb][nt][q] = 0.f;

#pragma unroll
    for (int kc = 0; kc < 8; kc++) {
        uint4 Ag[2], Ag8[2];
#pragma unroll
        for (int mb = 0; mb < 2; mb++) {
            int r1 = 32 * wr + 16 * mb + gid;
            Ag[mb]  = X4[r1 * XP + 4 * kc + tig];
            Ag8[mb] = X4[(r1 + 8) * XP + 4 * kc + tig];
        }
#pragma unroll
        for (int nt = 0; nt < 8; nt++) {
            int c = 64 * wn + 8 * nt + gid;
            uint4 Bv = Wt4[c * XP + 4 * kc + tig];
            const uint32_t* bn = reinterpret_cast<const uint32_t*>(&Bv);
#pragma unroll
            for (int ss = 0; ss < 2; ss++)
#pragma unroll
                for (int mb = 0; mb < 2; mb++) {
                    const uint32_t* ag  = reinterpret_cast<const uint32_t*>(&Ag[mb]);
                    const uint32_t* ag8 = reinterpret_cast<const uint32_t*>(&Ag8[mb]);
                    mma16(yacc[mb][nt], ag[2*ss], ag8[2*ss], ag[2*ss+1], ag8[2*ss+1],
                          bn[2*ss], bn[2*ss+1]);
                }
        }
    }
    __syncthreads();

#pragma unroll
    for (int mb = 0; mb < 2; mb++)
#pragma unroll
        for (int nt = 0; nt < 8; nt++) {
            int r1 = 32 * wr + 16 * mb + gid;
            int c  = 64 * wn + 8 * nt + 2 * tig;
            stg[c * 72 + r1]           = __float2half_rn(yacc[mb][nt][0]);
            stg[(c + 1) * 72 + r1]     = __float2half_rn(yacc[mb][nt][1]);
            stg[c * 72 + r1 + 8]       = __float2half_rn(yacc[mb][nt][2]);
            stg[(c + 1) * 72 + r1 + 8] = __float2half_rn(yacc[mb][nt][3]);
        }
    __syncthreads();

    int bb = row0 / HW_DIM, hw0 = row0 - bb * HW_DIM;
#pragma unroll
    for (int p = 0; p < 4; p++) {
        int c = p * 64 + (tid >> 2), ch = tid & 3;
        uint4 v  = *reinterpret_cast<const uint4*>(&stg[c * 72 + ch * 16]);
        uint4 v2 = *reinterpret_cast<const uint4*>(&stg[c * 72 + ch * 16 + 8]);
        *reinterpret_cast<uint4*>(
            &g_tt[((size_t)bb * C_DIM + c) * HW_DIM + hw0 + ch * 16]) = v;
        *reinterpret_cast<uint4*>(
            &g_tt[((size_t)bb * C_DIM + c) * HW_DIM + hw0 + ch * 16 + 8]) = v2;
    }
}

// ---------------------------------------------------------------------------
// Kernel C: fused pass, software-pipelined: each loop iteration executes
// ph1(m) AND ph2(m-1) interleaved (two independent mma chains per warp).
// S ping-pong through smem; 2 barriers/iter; loads double-buffered.
// 8 warps / 256 thr (best-known shape), warp grids as R10.
// ---------------------------------------------------------------------------
__global__ __launch_bounds__(256)
void ppm_fused(float* __restrict__ y) {
    extern __shared__ char smem[];
    uint32_t sbase = smem_u32(smem);
    const uint4* Xi4 = reinterpret_cast<const uint4*>(smem + SM_XI);

    int b  = blockIdx.y;
    int i0 = blockIdx.x * JT;
    const unsigned short* Xg = g_xn + (size_t)b * HW_DIM * C_DIM;
    const unsigned short* Tg = g_tt + (size_t)b * C_DIM * HW_DIM;

    int tid = threadIdx.x, w = tid >> 5, lane = tid & 31;
    int gid = lane >> 2, tig = lane & 3;
    int wr = w & 1, wn = w >> 1;

    const uint32_t xjOff[2] = {SM_XJ0, SM_XJ1};
    const uint32_t ttOff[2] = {SM_TT0, SM_TT1};
    const uint32_t ssOff[2] = {SM_SS0, SM_SS1};

    auto loadX = [&](int r0, uint32_t dstb) {
#pragma unroll
        for (int q = 0; q < 8; q++) {
            int idx = tid + q * 256, r = idx >> 5, c4 = idx & 31;
            cp16(sbase + dstb + (uint32_t)(r * XP + c4) * 16,
                 Xg + (size_t)(r0 + r) * C_DIM + c4 * 8);
        }
    };
    auto loadT = [&](int j0, uint32_t dstb) {
#pragma unroll
        for (int q = 0; q < 8; q++) {
            int idx = tid + q * 256, c = idx >> 3, k4 = idx & 7;
            cp16(sbase + dstb + (uint32_t)(c * TP + k4) * 16,
                 Tg + (size_t)c * HW_DIM + j0 + k4 * 8);
        }
    };

    // prologue: g0={Xi,Xj0,T0}, g1={Xj1,T1}
    loadX(i0, SM_XI);
    loadX(0, SM_XJ0);
    loadT(0, SM_TT0);
    CP_COMMIT();
    loadX(JT, SM_XJ1);
    loadT(JT, SM_TT1);
    CP_COMMIT();

    float yacc[2][8][4];
#pragma unroll
    for (int mb = 0; mb < 2; mb++)
#pragma unroll
        for (int nt = 0; nt < 8; nt++)
#pragma unroll
            for (int q = 0; q < 4; q++) yacc[mb][nt][q] = 0.f;

    // ---- iter 0: ph1(0) only
    CP_WAIT1();
    __syncthreads();
    {
        const uint4* Xj4 = reinterpret_cast<const uint4*>(smem + SM_XJ0);
        uint32_t* sSa = reinterpret_cast<uint32_t*>(smem + SM_SS0);
        float sacc[2][2][4] = {};
#pragma unroll
        for (int kc = 0; kc < 8; kc++) {
            uint4 Ag[2], Ag8[2], Bn[2];
#pragma unroll
            for (int mb = 0; mb < 2; mb++) {
                int r1 = 32 * wr + 16 * mb + gid;
                Ag[mb]  = Xi4[r1 * XP + 4 * kc + tig];
                Ag8[mb] = Xi4[(r1 + 8) * XP + 4 * kc + tig];
            }
#pragma unroll
            for (int nb = 0; nb < 2; nb++) {
                int n1 = 16 * wn + 8 * nb + gid;
                Bn[nb] = Xj4[n1 * XP + 4 * kc + tig];
            }
#pragma unroll
            for (int ss = 0; ss < 2; ss++)
#pragma unroll
                for (int mb = 0; mb < 2; mb++) {
                    const uint32_t* ag  = reinterpret_cast<const uint32_t*>(&Ag[mb]);
                    const uint32_t* ag8 = reinterpret_cast<const uint32_t*>(&Ag8[mb]);
#pragma unroll
                    for (int nb = 0; nb < 2; nb++) {
                        const uint32_t* bn = reinterpret_cast<const uint32_t*>(&Bn[nb]);
                        mma16(sacc[mb][nb], ag[2*ss], ag8[2*ss], ag[2*ss+1], ag8[2*ss+1],
                              bn[2*ss], bn[2*ss+1]);
                    }
                }
        }
#pragma unroll
        for (int mb = 0; mb < 2; mb++)
#pragma unroll
            for (int nb = 0; nb < 2; nb++) {
                int r1 = 32 * wr + 16 * mb + gid;
                int cw = 8 * wn + 4 * nb + tig;
                float v0 = fmaxf(sacc[mb][nb][0], 0.f), v1 = fmaxf(sacc[mb][nb][1], 0.f);
                float v2 = fmaxf(sacc[mb][nb][2], 0.f), v3 = fmaxf(sacc[mb][nb][3], 0.f);
                sSa[r1 * (SPW * 4) + cw]       = h2pack(v0 * v0, v1 * v1);
                sSa[(r1 + 8) * (SPW * 4) + cw] = h2pack(v2 * v2, v3 * v3);
            }
    }
    __syncthreads();
    loadX(2 * JT, SM_XJ0);
    CP_COMMIT();
    CP_WAIT1();
    __syncthreads();

    // ---- main loop: iteration m computes ph1(m) + ph2(m-1), interleaved
    for (int m = 1; m < NJT; m++) {
        int sa = m & 1, sp = sa ^ 1;
        const uint4* Xj4 = reinterpret_cast<const uint4*>(smem + xjOff[sa]);
        const uint4* T4  = reinterpret_cast<const uint4*>(smem + ttOff[sp]);
        const uint4* S4  = reinterpret_cast<const uint4*>(smem + ssOff[sp]);
        uint32_t*    sSa = reinterpret_cast<uint32_t*>(smem + ssOff[sa]);

        float sacc[2][2][4] = {};
        uint4 SA[2], SA8[2];
#pragma unroll
        for (int u = 0; u < 8; u++) {
            // --- ph1(m) chunk u: 8 mma, chain A
            uint4 Ag[2], Ag8[2], Bn[2];
#pragma unroll
            for (int mb = 0; mb < 2; mb++) {
                int r1 = 32 * wr + 16 * mb + gid;
                Ag[mb]  = Xi4[r1 * XP + 4 * u + tig];
                Ag8[mb] = Xi4[(r1 + 8) * XP + 4 * u + tig];
            }
#pragma unroll
            for (int nb = 0; nb < 2; nb++) {
                int n1 = 16 * wn + 8 * nb + gid;
                Bn[nb] = Xj4[n1 * XP + 4 * u + tig];
            }
#pragma unroll
            for (int ss = 0; ss < 2; ss++)
#pragma unroll
                for (int mb = 0; mb < 2; mb++) {
                    const uint32_t* ag  = reinterpret_cast<const uint32_t*>(&Ag[mb]);
                    const uint32_t* ag8 = reinterpret_cast<const uint32_t*>(&Ag8[mb]);
#pragma unroll
                    for (int nb = 0; nb < 2; nb++) {
                        const uint32_t* bn = reinterpret_cast<const uint32_t*>(&Bn[nb]);
                        mma16(sacc[mb][nb], ag[2*ss], ag8[2*ss], ag[2*ss+1], ag8[2*ss+1],
                              bn[2*ss], bn[2*ss+1]);
                    }
                }
            // --- ph2(m-1) chunk u: 8 mma, chain B (independent of chain A)
            int kc = u >> 2, nt0 = 2 * (u & 3);
            if ((u & 3) == 0) {
#pragma unroll
                for (int mb = 0; mb < 2; mb++) {
                    int r1 = 32 * wr + 16 * mb + gid;
                    SA[mb]  = S4[r1 * SPW + 4 * kc + tig];
                    SA8[mb] = S4[(r1 + 8) * SPW + 4 * kc + tig];
                }
            }
#pragma unroll
            for (int qq = 0; qq < 2; qq++) {
                int nt = nt0 + qq;
                int c = 64 * wn + 8 * nt + gid;
                uint4 Bv = T4[c * TP + 4 * kc + tig];
                const uint32_t* bn = reinterpret_cast<const uint32_t*>(&Bv);
#pragma unroll
                for (int ss = 0; ss < 2; ss++)
#pragma unroll
                    for (int mb = 0; mb < 2; mb++) {
                        const uint32_t* ag  = reinterpret_cast<const uint32_t*>(&SA[mb]);
                        const uint32_t* ag8 = reinterpret_cast<const uint32_t*>(&SA8[mb]);
                        mma16(yacc[mb][nt], ag[2*ss], ag8[2*ss], ag[2*ss+1], ag8[2*ss+1],
                              bn[2*ss], bn[2*ss+1]);
                    }
            }
        }
        // relu^2 -> sS[sa]
#pragma unroll
        for (int mb = 0; mb < 2; mb++)
#pragma unroll
            for (int nb = 0; nb < 2; nb++) {
                int r1 = 32 * wr + 16 * mb + gid;
                int cw = 8 * wn + 4 * nb + tig;
                float v0 = fmaxf(sacc[mb][nb][0], 0.f), v1 = fmaxf(sacc[mb][nb][1], 0.f);
                float v2 = fmaxf(sacc[mb][nb][2], 0.f), v3 = fmaxf(sacc[mb][nb][3], 0.f);
                sSa[r1 * (SPW * 4) + cw]       = h2pack(v0 * v0, v1 * v1);
                sSa[(r1 + 8) * (SPW * 4) + cw] = h2pack(v2 * v2, v3 * v3);
            }
        __syncthreads();                 // all reads of Xj[sa], T[sp], S[sp] done; S[sa] visible
        if (m + 2 < NJT) loadX((m + 2) * JT, xjOff[sa]);
        if (m + 1 < NJT) loadT((m + 1) * JT, ttOff[sp]);
        CP_COMMIT();
        CP_WAIT1();                      // group from iter m-1 (Xj(m+1), T(m)) complete
        __syncthreads();
    }

    // ---- epilogue: ph2(NJT-1)
    {
        int sl = (NJT - 1) & 1;
        const uint4* T4 = reinterpret_cast<const uint4*>(smem + ttOff[sl]);
        const uint4* S4 = reinterpret_cast<const uint4*>(smem + ssOff[sl]);
#pragma unroll
        for (int kc = 0; kc < 2; kc++) {
            uint4 SA[2], SA8[2];
#pragma unroll
            for (int mb = 0; mb < 2; mb++) {
                int r1 = 32 * wr + 16 * mb + gid;
                SA[mb]  = S4[r1 * SPW + 4 * kc + tig];
                SA8[mb] = S4[(r1 + 8) * SPW + 4 * kc + tig];
            }
#pragma unroll
            for (int nt = 0; nt < 8; nt++) {
                int c = 64 * wn + 8 * nt + gid;
                uint4 Bv = T4[c * TP + 4 * kc + tig];
                const uint32_t* bn = reinterpret_cast<const uint32_t*>(&Bv);
#pragma unroll
                for (int ss = 0; ss < 2; ss++)
#pragma unroll
                    for (int mb = 0; mb < 2; mb++) {
                        const uint32_t* ag  = reinterpret_cast<const uint32_t*>(&SA[mb]);
                        const uint32_t* ag8 = reinterpret_cast<const uint32_t*>(&SA8[mb]);
                        mma16(yacc[mb][nt], ag[2*ss], ag8[2*ss], ag[2*ss+1], ag8[2*ss+1],
                              bn[2*ss], bn[2*ss+1]);
                    }
            }
        }
    }

    // write Y
    float* Yb = y + ((size_t)b * HW_DIM + i0) * C_DIM;
#pragma unroll
    for (int mb = 0; mb < 2; mb++) {
        int r1 = 32 * wr + 16 * mb + gid;
#pragma unroll
        for (int nt = 0; nt < 8; nt++) {
            int c = 64 * wn + 8 * nt + 2 * tig;
            *reinterpret_cast<float2*>(&Yb[(size_t)r1 * C_DIM + c]) =
                make_float2(yacc[mb][nt][0], yacc[mb][nt][1]);
            *reinterpret_cast<float2*>(&Yb[(size_t)(r1 + 8) * C_DIM + c]) =
                make_float2(yacc[mb][nt][2], yacc[mb][nt][3]);
        }
    }
}

// ---------------------------------------------------------------------------
extern "C" void kernel_launch(void* const* d_in, const int* in_sizes, int n_in,
                              void* d_out, int out_size) {
    const float* x = (const float*)d_in[0];
    const float* W = (const float*)d_in[1];
    float* y = (float*)d_out;
    (void)in_sizes; (void)n_in; (void)out_size;

    norm_kernel<<<NROWS / 8, dim3(32, 8)>>>(x);
    wt_kernel<<<C_DIM, C_DIM>>>(W);

    cudaFuncSetAttribute(transform_mma, cudaFuncAttributeMaxDynamicSharedMemorySize, TM_TOT);
    transform_mma<<<NROWS / 64, 256, TM_TOT>>>();

    cudaFuncSetAttribute(ppm_fused, cudaFuncAttributeMaxDynamicSharedMemorySize, SM_TOT);
    ppm_fused<<<dim3(HW_DIM / JT, B_DIM), 256, SM_TOT>>>(y);
}

// round 15
// speedup vs baseline: 1.3137x; 1.0366x over previous
#include <cuda_runtime.h>
#include <cuda_fp16.h>
#include <math.h>
#include <stdint.h>

#define B_DIM   8
#define HW_DIM  3136
#define C_DIM   256
#define NROWS   (B_DIM * HW_DIM)        // 25088
#define JT      64                      // j tile
#define NJT     (HW_DIM / JT)           // 49

// fused smem (bytes). Xi fragment-major (contiguous, 32KB). Xj pitch 36 u4,
// T pitch 12 u4 (proven conflict-free). S fragment-major 8KB.
#define XP      36
#define TP      12
#define SM_XI   0                       // 32768
#define SM_XJ0  32768                   // 36864
#define SM_XJ1  69632                   // 36864
#define SM_TT0  106496                  // 49152
#define SM_TT1  155648                  // 49152
#define SM_SS   204800                  // 8192
#define SM_TOT  212992

// transform_mma smem
#define TM_WT   0
#define TM_XT   147456
#define TM_TOT  184320

// device-global scratch (fp16)
__device__ __align__(16) unsigned short g_xn[(size_t)NROWS * C_DIM];          // xn rows [row][c]
__device__ __align__(16) unsigned short g_xa[(size_t)NROWS * C_DIM];          // xn A-frag order
__device__ __align__(16) unsigned short g_xh[(size_t)NROWS * C_DIM];          // raw x fp16
__device__ __align__(16) unsigned short g_wt[(size_t)C_DIM * C_DIM];          // W^T [c][k]
__device__ __align__(16) unsigned short g_tt[(size_t)B_DIM * C_DIM * HW_DIM]; // t [b][c][hw]

__device__ __forceinline__ uint32_t h2pack(float a, float b) {
    __half2 h = __floats2half2_rn(a, b);
    return *reinterpret_cast<uint32_t*>(&h);
}
__device__ __forceinline__ uint32_t smem_u32(const void* p) {
    uint32_t a;
    asm("{ .reg .u64 t; cvta.to.shared.u64 t, %1; cvt.u32.u64 %0, t; }" : "=r"(a) : "l"(p));
    return a;
}
__device__ __forceinline__ void cp16(uint32_t dst, const void* src) {
    asm volatile("{ .reg .u64 g; cvta.to.global.u64 g, %1;"
                 " cp.async.cg.shared.global [%0], [g], 16; }" :: "r"(dst), "l"(src));
}
#define CP_COMMIT() asm volatile("cp.async.commit_group;" ::: "memory")
#define CP_WAIT0()  asm volatile("cp.async.wait_group 0;" ::: "memory")
#define CP_WAIT1()  asm volatile("cp.async.wait_group 1;" ::: "memory")

__device__ __forceinline__ void mma16(float* d, uint32_t a0, uint32_t a1,
                                      uint32_t a2, uint32_t a3,
                                      uint32_t b0, uint32_t b1) {
    asm volatile(
        "mma.sync.aligned.m16n8k16.row.col.f32.f16.f16.f32 "
        "{%0,%1,%2,%3}, {%4,%5,%6,%7}, {%8,%9}, {%0,%1,%2,%3};"
        : "+f"(d[0]), "+f"(d[1]), "+f"(d[2]), "+f"(d[3])
        : "r"(a0), "r"(a1), "r"(a2), "r"(a3), "r"(b0), "r"(b1));
}

// ---------------------------------------------------------------------------
// Kernel A: L2 normalize -> g_xn (fp16 rows) and raw x -> g_xh (fp16)
// ---------------------------------------------------------------------------
__global__ void norm_kernel(const float* __restrict__ x) {
    int row  = blockIdx.x * 8 + threadIdx.y;
    int lane = threadIdx.x;
    const float4* xr = reinterpret_cast<const float4*>(x) + (size_t)row * (C_DIM / 4);
    float4 v0 = xr[lane];
    float4 v1 = xr[lane + 32];
    float s = v0.x*v0.x + v0.y*v0.y + v0.z*v0.z + v0.w*v0.w
            + v1.x*v1.x + v1.y*v1.y + v1.z*v1.z + v1.w*v1.w;
#pragma unroll
    for (int off = 16; off > 0; off >>= 1) s += __shfl_xor_sync(0xffffffffu, s, off);
    float inv = rsqrtf(fmaxf(s, 1e-12f));
    uint2* oh = reinterpret_cast<uint2*>(g_xh) + (size_t)row * (C_DIM / 4);
    oh[lane]      = make_uint2(h2pack(v0.x, v0.y), h2pack(v0.z, v0.w));
    oh[lane + 32] = make_uint2(h2pack(v1.x, v1.y), h2pack(v1.z, v1.w));
    uint2* o = reinterpret_cast<uint2*>(g_xn) + (size_t)row * (C_DIM / 4);
    o[lane]      = make_uint2(h2pack(v0.x*inv, v0.y*inv), h2pack(v0.z*inv, v0.w*inv));
    o[lane + 32] = make_uint2(h2pack(v1.x*inv, v1.y*inv), h2pack(v1.z*inv, v1.w*inv));
}

// ---------------------------------------------------------------------------
// Kernel A2: W^T -> g_wt[c][k] fp16
// ---------------------------------------------------------------------------
__global__ void wt_kernel(const float* __restrict__ W) {
    int c = blockIdx.x, k = threadIdx.x;
    g_wt[(size_t)c * C_DIM + k] = __half_as_ushort(__float2half_rn(W[(size_t)k * C_DIM + c]));
}

// ---------------------------------------------------------------------------
// Kernel A3: relayout g_xn -> g_xa in A-fragment order.
//   Per 16-row group g, chunk (kc,ss) [16 chunks], lane l (gid=l>>2,tig=l&3):
//   16B = { X[16g+gid][k0..k0+1], X[16g+gid+8][k0..+1],
//           X[16g+gid][k0+2..+3], X[16g+gid+8][k0+2..+3] }, k0=8*(4kc+tig)+4ss
// ---------------------------------------------------------------------------
__global__ __launch_bounds__(256)
void xa_kernel() {
    __shared__ unsigned short sx[64 * 272];
    size_t row0 = (size_t)blockIdx.x * 64;
    int tid = threadIdx.x;
#pragma unroll
    for (int q = 0; q < 8; q++) {
        int idx = tid + q * 256, r = idx >> 5, c4 = idx & 31;
        *reinterpret_cast<uint4*>(&sx[r * 272 + c4 * 8]) =
            *reinterpret_cast<const uint4*>(&g_xn[(row0 + r) * C_DIM + c4 * 8]);
    }
    __syncthreads();
#pragma unroll
    for (int q = 0; q < 8; q++) {
        int o = tid + q * 256;                  // 0..2047
        int g = o >> 9, chunk = (o >> 5) & 15, lane = o & 31;
        int gid = lane >> 2, tig = lane & 3;
        int kc = chunk >> 1, ss = chunk & 1;
        int k0 = 8 * (4 * kc + tig) + 4 * ss;
        int rb = g * 16 + gid;
        uint32_t w0 = *reinterpret_cast<const uint32_t*>(&sx[rb * 272 + k0]);
        uint32_t w1 = *reinterpret_cast<const uint32_t*>(&sx[(rb + 8) * 272 + k0]);
        uint32_t w2 = *reinterpret_cast<const uint32_t*>(&sx[rb * 272 + k0 + 2]);
        uint32_t w3 = *reinterpret_cast<const uint32_t*>(&sx[(rb + 8) * 272 + k0 + 2]);
        *reinterpret_cast<uint4*>(&g_xa[row0 * C_DIM + (size_t)o * 8]) =
            make_uint4(w0, w1, w2, w3);
    }
}

// ---------------------------------------------------------------------------
// Kernel B: t = x @ W on fp16 tensor cores; stored transposed: g_tt[b][c][hw]
// ---------------------------------------------------------------------------
__global__ __launch_bounds__(256)
void transform_mma() {
    extern __shared__ char smem[];
    uint32_t sbase = smem_u32(smem);
    const uint4* Wt4 = reinterpret_cast<const uint4*>(smem + TM_WT);
    const uint4* X4  = reinterpret_cast<const uint4*>(smem + TM_XT);
    __half*      stg = reinterpret_cast<__half*>(smem + TM_XT);

    int row0 = blockIdx.x * 64;
    int tid = threadIdx.x, w = tid >> 5, lane = tid & 31;
    int gid = lane >> 2, tig = lane & 3;
    int wr = w & 1, wn = w >> 1;

#pragma unroll
    for (int q = 0; q < 32; q++) {
        int idx = tid + q * 256, r = idx >> 5, c4 = idx & 31;
        cp16(sbase + TM_WT + (uint32_t)(r * XP + c4) * 16,
             g_wt + (size_t)r * C_DIM + c4 * 8);
    }
#pragma unroll
    for (int q = 0; q < 8; q++) {
        int idx = tid + q * 256, r = idx >> 5, c4 = idx & 31;
        cp16(sbase + TM_XT + (uint32_t)(r * XP + c4) * 16,
             g_xh + (size_t)(row0 + r) * C_DIM + c4 * 8);
    }
    CP_COMMIT(); CP_WAIT0();
    __syncthreads();

    float yacc[2][8][4];
#pragma unroll
    for (int mb = 0; mb < 2; mb++)
#pragma unroll
        for (int nt = 0; nt < 8; nt++)
#pragma unroll
            for (int q = 0; q < 4; q++) yacc[mb][nt][q] = 0.f;

#pragma unroll
    for (int kc = 0; kc < 8; kc++) {
        uint4 Ag[2], Ag8[2];
#pragma unroll
        for (int mb = 0; mb < 2; mb++) {
            int r1 = 32 * wr + 16 * mb + gid;
            Ag[mb]  = X4[r1 * XP + 4 * kc + tig];
            Ag8[mb] = X4[(r1 + 8) * XP + 4 * kc + tig];
        }
#pragma unroll
        for (int nt = 0; nt < 8; nt++) {
            int c = 64 * wn + 8 * nt + gid;
            uint4 Bv = Wt4[c * XP + 4 * kc + tig];
            const uint32_t* bn = reinterpret_cast<const uint32_t*>(&Bv);
#pragma unroll
            for (int ss = 0; ss < 2; ss++)
#pragma unroll
                for (int mb = 0; mb < 2; mb++) {
                    const uint32_t* ag  = reinterpret_cast<const uint32_t*>(&Ag[mb]);
                    const uint32_t* ag8 = reinterpret_cast<const uint32_t*>(&Ag8[mb]);
                    mma16(yacc[mb][nt], ag[2*ss], ag8[2*ss], ag[2*ss+1], ag8[2*ss+1],
                          bn[2*ss], bn[2*ss+1]);
                }
        }
    }
    __syncthreads();

#pragma unroll
    for (int mb = 0; mb < 2; mb++)
#pragma unroll
        for (int nt = 0; nt < 8; nt++) {
            int r1 = 32 * wr + 16 * mb + gid;
            int c  = 64 * wn + 8 * nt + 2 * tig;
            stg[c * 72 + r1]           = __float2half_rn(yacc[mb][nt][0]);
            stg[(c + 1) * 72 + r1]     = __float2half_rn(yacc[mb][nt][1]);
            stg[c * 72 + r1 + 8]       = __float2half_rn(yacc[mb][nt][2]);
            stg[(c + 1) * 72 + r1 + 8] = __float2half_rn(yacc[mb][nt][3]);
        }
    __syncthreads();

    int bb = row0 / HW_DIM, hw0 = row0 - bb * HW_DIM;
#pragma unroll
    for (int p = 0; p < 4; p++) {
        int c = p * 64 + (tid >> 2), ch = tid & 3;
        uint4 v  = *reinterpret_cast<const uint4*>(&stg[c * 72 + ch * 16]);
        uint4 v2 = *reinterpret_cast<const uint4*>(&stg[c * 72 + ch * 16 + 8]);
        *reinterpret_cast<uint4*>(
            &g_tt[((size_t)bb * C_DIM + c) * HW_DIM + hw0 + ch * 16]) = v;
        *reinterpret_cast<uint4*>(
            &g_tt[((size_t)bb * C_DIM + c) * HW_DIM + hw0 + ch * 16 + 8]) = v2;
    }
}

// ---------------------------------------------------------------------------
// Kernel C: fused pass; A operands fragment-major (one aligned LDS.128 quad
// per mma A) -> zero operand-marshalling MOVs. Structure = R10 (proven).
// ---------------------------------------------------------------------------
__global__ __launch_bounds__(256)
void ppm_fused(float* __restrict__ y) {
    extern __shared__ char smem[];
    uint32_t sbase = smem_u32(smem);
    const uint4* XiF = reinterpret_cast<const uint4*>(smem + SM_XI);
    const uint4* S4  = reinterpret_cast<const uint4*>(smem + SM_SS);
    uint32_t*    sS  = reinterpret_cast<uint32_t*>(smem + SM_SS);

    int b  = blockIdx.y;
    int i0 = blockIdx.x * JT;
    const unsigned short* Xg = g_xn + (size_t)b * HW_DIM * C_DIM;
    const unsigned short* Agm = g_xa + ((size_t)b * HW_DIM + i0) * C_DIM;
    const unsigned short* Tg = g_tt + (size_t)b * C_DIM * HW_DIM;

    int tid = threadIdx.x, w = tid >> 5, lane = tid & 31;
    int gid = lane >> 2, tig = lane & 3;
    int wr = w & 1, wn = w >> 1;

    const uint32_t xjOff[2] = {SM_XJ0, SM_XJ1};
    const uint32_t ttOff[2] = {SM_TT0, SM_TT1};

    auto loadX = [&](int r0, uint32_t dstb) {
#pragma unroll
        for (int q = 0; q < 8; q++) {
            int idx = tid + q * 256, r = idx >> 5, c4 = idx & 31;
            cp16(sbase + dstb + (uint32_t)(r * XP + c4) * 16,
                 Xg + (size_t)(r0 + r) * C_DIM + c4 * 8);
        }
    };
    auto loadT = [&](int j0, uint32_t dstb) {
#pragma unroll
        for (int q = 0; q < 8; q++) {
            int idx = tid + q * 256, c = idx >> 3, k4 = idx & 7;
            cp16(sbase + dstb + (uint32_t)(c * TP + k4) * 16,
                 Tg + (size_t)c * HW_DIM + j0 + k4 * 8);
        }
    };

    // prologue: g0={Xi(frag),Xj0,T0}, g1={Xj1,T1}
#pragma unroll
    for (int q = 0; q < 8; q++) {
        int idx = tid + q * 256;
        cp16(sbase + SM_XI + (uint32_t)idx * 16, Agm + (size_t)idx * 8);
    }
    loadX(0, SM_XJ0);
    loadT(0, SM_TT0);
    CP_COMMIT();
    loadX(JT, SM_XJ1);
    loadT(JT, SM_TT1);
    CP_COMMIT();

    float yacc[2][8][4];
#pragma unroll
    for (int mb = 0; mb < 2; mb++)
#pragma unroll
        for (int nt = 0; nt < 8; nt++)
#pragma unroll
            for (int q = 0; q < 4; q++) yacc[mb][nt][q] = 0.f;

    for (int j = 0; j < NJT; j++) {
        int s = j & 1;
        if (j == NJT - 1) CP_WAIT0(); else CP_WAIT1();
        __syncthreads();
        const uint4* Xj4 = reinterpret_cast<const uint4*>(smem + xjOff[s]);
        const uint4* T4  = reinterpret_cast<const uint4*>(smem + ttOff[s]);

        // ---- phase 1: S(32x16/warp) = Xi @ Xj^T over K=256
        float sacc[2][2][4] = {};
#pragma unroll
        for (int kc = 0; kc < 8; kc++) {
            uint4 Aq[2][2];                 // [mb][ss] aligned quads
#pragma unroll
            for (int mb = 0; mb < 2; mb++)
#pragma unroll
                for (int ss = 0; ss < 2; ss++)
                    Aq[mb][ss] = XiF[((2 * wr + mb) * 16 + 2 * kc + ss) * 32 + lane];
            uint4 Bn[2];
#pragma unroll
            for (int nb = 0; nb < 2; nb++)
                Bn[nb] = Xj4[(16 * wn + 8 * nb + gid) * XP + 4 * kc + tig];
#pragma unroll
            for (int ss = 0; ss < 2; ss++)
#pragma unroll
                for (int mb = 0; mb < 2; mb++) {
                    uint4 a = Aq[mb][ss];
#pragma unroll
                    for (int nb = 0; nb < 2; nb++) {
                        const uint32_t* bn = reinterpret_cast<const uint32_t*>(&Bn[nb]);
                        mma16(sacc[mb][nb], a.x, a.y, a.z, a.w, bn[2*ss], bn[2*ss+1]);
                    }
                }
        }
        // relu^2 -> sS in ph2 A-fragment order
#pragma unroll
        for (int mb = 0; mb < 2; mb++)
#pragma unroll
            for (int nb = 0; nb < 2; nb++) {
                int gp = 2 * wr + mb;
                int wv = 8 * wn + 4 * nb + tig;        // S col word index
                int qh = wv & 1, ss2 = (wv >> 1) & 1, u = wv >> 2;
                int kc2 = u >> 2, tigc = u & 3;
                int lanec = 4 * gid + tigc;
                uint32_t waddr = ((uint32_t)(gp * 4 + kc2 * 2 + ss2) * 32 + lanec) * 4 + 2 * qh;
                float v0 = fmaxf(sacc[mb][nb][0], 0.f), v1 = fmaxf(sacc[mb][nb][1], 0.f);
                float v2 = fmaxf(sacc[mb][nb][2], 0.f), v3 = fmaxf(sacc[mb][nb][3], 0.f);
                *reinterpret_cast<uint2*>(&sS[waddr]) =
                    make_uint2(h2pack(v0 * v0, v1 * v1), h2pack(v2 * v2, v3 * v3));
            }
        __syncthreads();

        if (j + 2 < NJT) loadX((j + 2) * JT, xjOff[s]);

        // ---- phase 2: Y(32x64/warp) += S @ T over K=64
#pragma unroll
        for (int kc2 = 0; kc2 < 2; kc2++) {
            uint4 Sq[2][2];                 // [mb][ss] aligned quads
#pragma unroll
            for (int mb = 0; mb < 2; mb++)
#pragma unroll
                for (int ss = 0; ss < 2; ss++)
                    Sq[mb][ss] = S4[((2 * wr + mb) * 4 + kc2 * 2 + ss) * 32 + lane];
#pragma unroll
            for (int nt = 0; nt < 8; nt++) {
                int c = 64 * wn + 8 * nt + gid;
                uint4 Bv = T4[c * TP + 4 * kc2 + tig];
                const uint32_t* bn = reinterpret_cast<const uint32_t*>(&Bv);
#pragma unroll
                for (int ss = 0; ss < 2; ss++)
#pragma unroll
                    for (int mb = 0; mb < 2; mb++) {
                        uint4 a = Sq[mb][ss];
                        mma16(yacc[mb][nt], a.x, a.y, a.z, a.w, bn[2*ss], bn[2*ss+1]);
                    }
            }
        }
        __syncthreads();

        if (j + 2 < NJT) { loadT((j + 2) * JT, ttOff[s]); CP_COMMIT(); }
    }

    // epilogue
    float* Yb = y + ((size_t)b * HW_DIM + i0) * C_DIM;
#pragma unroll
    for (int mb = 0; mb < 2; mb++) {
        int r1 = 32 * wr + 16 * mb + gid;
#pragma unroll
        for (int nt = 0; nt < 8; nt++) {
            int c = 64 * wn + 8 * nt + 2 * tig;
            *reinterpret_cast<float2*>(&Yb[(size_t)r1 * C_DIM + c]) =
                make_float2(yacc[mb][nt][0], yacc[mb][nt][1]);
            *reinterpret_cast<float2*>(&Yb[(size_t)(r1 + 8) * C_DIM + c]) =
                make_float2(yacc[mb][nt][2], yacc[mb][nt][3]);
        }
    }
}

// ---------------------------------------------------------------------------
extern "C" void kernel_launch(void* const* d_in, const int* in_sizes, int n_in,
                              void* d_out, int out_size) {
    const float* x = (const float*)d_in[0];
    const float* W = (const float*)d_in[1];
    float* y = (float*)d_out;
    (void)in_sizes; (void)n_in; (void)out_size;

    norm_kernel<<<NROWS / 8, dim3(32, 8)>>>(x);
    wt_kernel<<<C_DIM, C_DIM>>>(W);
    xa_kernel<<<NROWS / 64, 256>>>();

    cudaFuncSetAttribute(transform_mma, cudaFuncAttributeMaxDynamicSharedMemorySize, TM_TOT);
    transform_mma<<<NROWS / 64, 256, TM_TOT>>>();

    cudaFuncSetAttribute(ppm_fused, cudaFuncAttributeMaxDynamicSharedMemorySize, SM_TOT);
    ppm_fused<<<dim3(HW_DIM / JT, B_DIM), 256, SM_TOT>>>(y);
}

// round 16
// speedup vs baseline: 1.5018x; 1.1432x over previous
#include <cuda_runtime.h>
#include <cuda_fp16.h>
#include <math.h>
#include <stdint.h>

#define B_DIM   8
#define HW_DIM  3136
#define C_DIM   256
#define NROWS   (B_DIM * HW_DIM)        // 25088
#define JT      64                      // j tile
#define NJT     (HW_DIM / JT)           // 49

// fused smem (bytes). Xi fragment-major (contiguous, 32KB). Xj pitch 36 u4,
// T pitch 12 u4 (proven conflict-free). S fragment-major 8KB.
#define XP      36
#define TP      12
#define SM_XI   0                       // 32768
#define SM_XJ0  32768                   // 36864
#define SM_XJ1  69632                   // 36864
#define SM_TT0  106496                  // 49152
#define SM_TT1  155648                  // 49152
#define SM_SS   204800                  // 8192
#define SM_TOT  212992

// transform_mma smem
#define TM_WT   0
#define TM_XT   147456
#define TM_TOT  184320

// device-global scratch (fp16)
__device__ __align__(16) unsigned short g_xn[(size_t)NROWS * C_DIM];          // xn rows [row][c]
__device__ __align__(16) unsigned short g_xa[(size_t)NROWS * C_DIM];          // xn A-frag order
__device__ __align__(16) unsigned short g_xh[(size_t)NROWS * C_DIM];          // raw x fp16
__device__ __align__(16) unsigned short g_wt[(size_t)C_DIM * C_DIM];          // W^T [c][k]
__device__ __align__(16) unsigned short g_tt[(size_t)B_DIM * C_DIM * HW_DIM]; // t [b][c][hw]

__device__ __forceinline__ uint32_t h2pack(float a, float b) {
    __half2 h = __floats2half2_rn(a, b);
    return *reinterpret_cast<uint32_t*>(&h);
}
__device__ __forceinline__ uint32_t smem_u32(const void* p) {
    uint32_t a;
    asm("{ .reg .u64 t; cvta.to.shared.u64 t, %1; cvt.u32.u64 %0, t; }" : "=r"(a) : "l"(p));
    return a;
}
__device__ __forceinline__ void cp16(uint32_t dst, const void* src) {
    asm volatile("{ .reg .u64 g; cvta.to.global.u64 g, %1;"
                 " cp.async.cg.shared.global [%0], [g], 16; }" :: "r"(dst), "l"(src));
}
#define CP_COMMIT() asm volatile("cp.async.commit_group;" ::: "memory")
#define CP_WAIT0()  asm volatile("cp.async.wait_group 0;" ::: "memory")
#define CP_WAIT1()  asm volatile("cp.async.wait_group 1;" ::: "memory")

__device__ __forceinline__ void mma16(float* d, uint32_t a0, uint32_t a1,
                                      uint32_t a2, uint32_t a3,
                                      uint32_t b0, uint32_t b1) {
    asm volatile(
        "mma.sync.aligned.m16n8k16.row.col.f32.f16.f16.f32 "
        "{%0,%1,%2,%3}, {%4,%5,%6,%7}, {%8,%9}, {%0,%1,%2,%3};"
        : "+f"(d[0]), "+f"(d[1]), "+f"(d[2]), "+f"(d[3])
        : "r"(a0), "r"(a1), "r"(a2), "r"(a3), "r"(b0), "r"(b1));
}

// ---------------------------------------------------------------------------
// Kernel A: L2 normalize -> g_xn (fp16 rows) and raw x -> g_xh (fp16)
// ---------------------------------------------------------------------------
__global__ void norm_kernel(const float* __restrict__ x) {
    int row  = blockIdx.x * 8 + threadIdx.y;
    int lane = threadIdx.x;
    const float4* xr = reinterpret_cast<const float4*>(x) + (size_t)row * (C_DIM / 4);
    float4 v0 = xr[lane];
    float4 v1 = xr[lane + 32];
    float s = v0.x*v0.x + v0.y*v0.y + v0.z*v0.z + v0.w*v0.w
            + v1.x*v1.x + v1.y*v1.y + v1.z*v1.z + v1.w*v1.w;
#pragma unroll
    for (int off = 16; off > 0; off >>= 1) s += __shfl_xor_sync(0xffffffffu, s, off);
    float inv = rsqrtf(fmaxf(s, 1e-12f));
    uint2* oh = reinterpret_cast<uint2*>(g_xh) + (size_t)row * (C_DIM / 4);
    oh[lane]      = make_uint2(h2pack(v0.x, v0.y), h2pack(v0.z, v0.w));
    oh[lane + 32] = make_uint2(h2pack(v1.x, v1.y), h2pack(v1.z, v1.w));
    uint2* o = reinterpret_cast<uint2*>(g_xn) + (size_t)row * (C_DIM / 4);
    o[lane]      = make_uint2(h2pack(v0.x*inv, v0.y*inv), h2pack(v0.z*inv, v0.w*inv));
    o[lane + 32] = make_uint2(h2pack(v1.x*inv, v1.y*inv), h2pack(v1.z*inv, v1.w*inv));
}

// ---------------------------------------------------------------------------
// Kernel A2: W^T -> g_wt[c][k] fp16
// ---------------------------------------------------------------------------
__global__ void wt_kernel(const float* __restrict__ W) {
    int c = blockIdx.x, k = threadIdx.x;
    g_wt[(size_t)c * C_DIM + k] = __half_as_ushort(__float2half_rn(W[(size_t)k * C_DIM + c]));
}

// ---------------------------------------------------------------------------
// Kernel A3: relayout g_xn -> g_xa in A-fragment order (proven in R14).
// ---------------------------------------------------------------------------
__global__ __launch_bounds__(256)
void xa_kernel() {
    __shared__ unsigned short sx[64 * 272];
    size_t row0 = (size_t)blockIdx.x * 64;
    int tid = threadIdx.x;
#pragma unroll
    for (int q = 0; q < 8; q++) {
        int idx = tid + q * 256, r = idx >> 5, c4 = idx & 31;
        *reinterpret_cast<uint4*>(&sx[r * 272 + c4 * 8]) =
            *reinterpret_cast<const uint4*>(&g_xn[(row0 + r) * C_DIM + c4 * 8]);
    }
    __syncthreads();
#pragma unroll
    for (int q = 0; q < 8; q++) {
        int o = tid + q * 256;
        int g = o >> 9, chunk = (o >> 5) & 15, lane = o & 31;
        int gid = lane >> 2, tig = lane & 3;
        int kc = chunk >> 1, ss = chunk & 1;
        int k0 = 8 * (4 * kc + tig) + 4 * ss;
        int rb = g * 16 + gid;
        uint32_t w0 = *reinterpret_cast<const uint32_t*>(&sx[rb * 272 + k0]);
        uint32_t w1 = *reinterpret_cast<const uint32_t*>(&sx[(rb + 8) * 272 + k0]);
        uint32_t w2 = *reinterpret_cast<const uint32_t*>(&sx[rb * 272 + k0 + 2]);
        uint32_t w3 = *reinterpret_cast<const uint32_t*>(&sx[(rb + 8) * 272 + k0 + 2]);
        *reinterpret_cast<uint4*>(&g_xa[row0 * C_DIM + (size_t)o * 8]) =
            make_uint4(w0, w1, w2, w3);
    }
}

// ---------------------------------------------------------------------------
// Kernel B: t = x @ W on fp16 tensor cores; stored transposed: g_tt[b][c][hw]
// ---------------------------------------------------------------------------
__global__ __launch_bounds__(256)
void transform_mma() {
    extern __shared__ char smem[];
    uint32_t sbase = smem_u32(smem);
    const uint4* Wt4 = reinterpret_cast<const uint4*>(smem + TM_WT);
    const uint4* X4  = reinterpret_cast<const uint4*>(smem + TM_XT);
    __half*      stg = reinterpret_cast<__half*>(smem + TM_XT);

    int row0 = blockIdx.x * 64;
    int tid = threadIdx.x, w = tid >> 5, lane = tid & 31;
    int gid = lane >> 2, tig = lane & 3;
    int wr = w & 1, wn = w >> 1;

#pragma unroll
    for (int q = 0; q < 32; q++) {
        int idx = tid + q * 256, r = idx >> 5, c4 = idx & 31;
        cp16(sbase + TM_WT + (uint32_t)(r * XP + c4) * 16,
             g_wt + (size_t)r * C_DIM + c4 * 8);
    }
#pragma unroll
    for (int q = 0; q < 8; q++) {
        int idx = tid + q * 256, r = idx >> 5, c4 = idx & 31;
        cp16(sbase + TM_XT + (uint32_t)(r * XP + c4) * 16,
             g_xh + (size_t)(row0 + r) * C_DIM + c4 * 8);
    }
    CP_COMMIT(); CP_WAIT0();
    __syncthreads();

    float yacc[2][8][4];
#pragma unroll
    for (int mb = 0; mb < 2; mb++)
#pragma unroll
        for (int nt = 0; nt < 8; nt++)
#pragma unroll
            for (int q = 0; q < 4; q++) yacc[mb][nt][q] = 0.f;

#pragma unroll
    for (int kc = 0; kc < 8; kc++) {
        uint4 Ag[2], Ag8[2];
#pragma unroll
        for (int mb = 0; mb < 2; mb++) {
            int r1 = 32 * wr + 16 * mb + gid;
            Ag[mb]  = X4[r1 * XP + 4 * kc + tig];
            Ag8[mb] = X4[(r1 + 8) * XP + 4 * kc + tig];
        }
#pragma unroll
        for (int nt = 0; nt < 8; nt++) {
            int c = 64 * wn + 8 * nt + gid;
            uint4 Bv = Wt4[c * XP + 4 * kc + tig];
            const uint32_t* bn = reinterpret_cast<const uint32_t*>(&Bv);
#pragma unroll
            for (int ss = 0; ss < 2; ss++)
#pragma unroll
                for (int mb = 0; mb < 2; mb++) {
                    const uint32_t* ag  = reinterpret_cast<const uint32_t*>(&Ag[mb]);
                    const uint32_t* ag8 = reinterpret_cast<const uint32_t*>(&Ag8[mb]);
                    mma16(yacc[mb][nt], ag[2*ss], ag8[2*ss], ag[2*ss+1], ag8[2*ss+1],
                          bn[2*ss], bn[2*ss+1]);
                }
        }
    }
    __syncthreads();

#pragma unroll
    for (int mb = 0; mb < 2; mb++)
#pragma unroll
        for (int nt = 0; nt < 8; nt++) {
            int r1 = 32 * wr + 16 * mb + gid;
            int c  = 64 * wn + 8 * nt + 2 * tig;
            stg[c * 72 + r1]           = __float2half_rn(yacc[mb][nt][0]);
            stg[(c + 1) * 72 + r1]     = __float2half_rn(yacc[mb][nt][1]);
            stg[c * 72 + r1 + 8]       = __float2half_rn(yacc[mb][nt][2]);
            stg[(c + 1) * 72 + r1 + 8] = __float2half_rn(yacc[mb][nt][3]);
        }
    __syncthreads();

    int bb = row0 / HW_DIM, hw0 = row0 - bb * HW_DIM;
#pragma unroll
    for (int p = 0; p < 4; p++) {
        int c = p * 64 + (tid >> 2), ch = tid & 3;
        uint4 v  = *reinterpret_cast<const uint4*>(&stg[c * 72 + ch * 16]);
        uint4 v2 = *reinterpret_cast<const uint4*>(&stg[c * 72 + ch * 16 + 8]);
        *reinterpret_cast<uint4*>(
            &g_tt[((size_t)bb * C_DIM + c) * HW_DIM + hw0 + ch * 16]) = v;
        *reinterpret_cast<uint4*>(
            &g_tt[((size_t)bb * C_DIM + c) * HW_DIM + hw0 + ch * 16 + 8]) = v2;
    }
}

// ---------------------------------------------------------------------------
// Kernel C: fused pass; all in-loop smem accesses are loop-invariant-base +
// compile-time-immediate (j-loop unrolled by 2 so buffer parity is constant;
// per-thread base pointers hoisted). Semantics identical to R14.
// ---------------------------------------------------------------------------
__global__ __launch_bounds__(256)
void ppm_fused(float* __restrict__ y) {
    extern __shared__ char smem[];
    uint32_t sbase = smem_u32(smem);
    const uint4* XiF = reinterpret_cast<const uint4*>(smem + SM_XI);
    const uint4* S4  = reinterpret_cast<const uint4*>(smem + SM_SS);
    uint32_t*    sS  = reinterpret_cast<uint32_t*>(smem + SM_SS);

    int b  = blockIdx.y;
    int i0 = blockIdx.x * JT;
    const unsigned short* Xg  = g_xn + (size_t)b * HW_DIM * C_DIM;
    const unsigned short* Agm = g_xa + ((size_t)b * HW_DIM + i0) * C_DIM;
    const unsigned short* Tg  = g_tt + (size_t)b * C_DIM * HW_DIM;

    int tid = threadIdx.x, w = tid >> 5, lane = tid & 31;
    int gid = lane >> 2, tig = lane & 3;
    int wr = w & 1, wn = w >> 1;

    // --- hoisted per-thread bases (all in-loop offsets are constants) ---
    const uint4* aXi  = XiF + (2 * wr * 16) * 32 + lane;
    const uint4* xjB0 = reinterpret_cast<const uint4*>(smem + SM_XJ0) + (16 * wn + gid) * XP + tig;
    const uint4* xjB1 = reinterpret_cast<const uint4*>(smem + SM_XJ1) + (16 * wn + gid) * XP + tig;
    const uint4* ttB0 = reinterpret_cast<const uint4*>(smem + SM_TT0) + (64 * wn + gid) * TP + tig;
    const uint4* ttB1 = reinterpret_cast<const uint4*>(smem + SM_TT1) + (64 * wn + gid) * TP + tig;
    const uint4* sqB  = S4 + (2 * wr * 4) * 32 + lane;
    uint32_t* sstore[2][2];
#pragma unroll
    for (int mb = 0; mb < 2; mb++)
#pragma unroll
        for (int nb = 0; nb < 2; nb++) {
            int gp = 2 * wr + mb;
            int wv = 8 * wn + 4 * nb + tig;
            int qh = wv & 1, ss2 = (wv >> 1) & 1, u = wv >> 2;
            int kc2 = u >> 2, tigc = u & 3;
            int lanec = 4 * gid + tigc;
            sstore[mb][nb] = sS + ((uint32_t)(gp * 4 + kc2 * 2 + ss2) * 32 + lanec) * 4 + 2 * qh;
        }

    // --- strided loaders (bases hoisted; strides compile-time) ---
    const unsigned short* xsrcB = Xg + (size_t)(tid >> 5) * C_DIM + (tid & 31) * 8;
    uint32_t xdst0 = sbase + SM_XJ0 + (uint32_t)((tid >> 5) * XP + (tid & 31)) * 16;
    uint32_t xdst1 = xdst0 + (SM_XJ1 - SM_XJ0);
    const unsigned short* tsrcB = Tg + (size_t)(tid >> 3) * HW_DIM + (tid & 7) * 8;
    uint32_t tdst0 = sbase + SM_TT0 + (uint32_t)((tid >> 3) * TP + (tid & 7)) * 16;
    uint32_t tdst1 = tdst0 + (SM_TT1 - SM_TT0);

    auto loadX = [&](int r0, uint32_t d) {
        const unsigned short* s = xsrcB + (size_t)r0 * C_DIM;
#pragma unroll
        for (int q = 0; q < 8; q++)
            cp16(d + (uint32_t)q * (8 * XP * 16), s + (size_t)q * 8 * C_DIM);
    };
    auto loadT = [&](int j0, uint32_t d) {
        const unsigned short* s = tsrcB + j0;
#pragma unroll
        for (int q = 0; q < 8; q++)
            cp16(d + (uint32_t)q * (32 * TP * 16), s + (size_t)q * 32 * HW_DIM);
    };

    // prologue: g0={Xi(frag),Xj0,T0}, g1={Xj1,T1}
#pragma unroll
    for (int q = 0; q < 8; q++) {
        int idx = tid + q * 256;
        cp16(sbase + SM_XI + (uint32_t)idx * 16, Agm + (size_t)idx * 8);
    }
    loadX(0, xdst0);
    loadT(0, tdst0);
    CP_COMMIT();
    loadX(JT, xdst1);
    loadT(JT, tdst1);
    CP_COMMIT();

    float yacc[2][8][4];
#pragma unroll
    for (int mb = 0; mb < 2; mb++)
#pragma unroll
        for (int nt = 0; nt < 8; nt++)
#pragma unroll
            for (int q = 0; q < 4; q++) yacc[mb][nt][q] = 0.f;

    // one fused iteration; all smem ops are base+constant. Inlined lambda.
    auto iter = [&](int j, const uint4* xjB, const uint4* ttB,
                    uint32_t xdst, uint32_t tdst, bool last) {
        if (last) CP_WAIT0(); else CP_WAIT1();
        __syncthreads();

        // phase 1: S(32x16/warp) = Xi @ Xj^T over K=256
        float sacc[2][2][4] = {};
#pragma unroll
        for (int kc = 0; kc < 8; kc++) {
            uint4 Aq[2][2];
#pragma unroll
            for (int mb = 0; mb < 2; mb++)
#pragma unroll
                for (int ss = 0; ss < 2; ss++)
                    Aq[mb][ss] = aXi[(mb * 16 + 2 * kc + ss) * 32];
            uint4 Bn[2];
#pragma unroll
            for (int nb = 0; nb < 2; nb++)
                Bn[nb] = xjB[8 * nb * XP + 4 * kc];
#pragma unroll
            for (int ss = 0; ss < 2; ss++)
#pragma unroll
                for (int mb = 0; mb < 2; mb++) {
                    uint4 a = Aq[mb][ss];
#pragma unroll
                    for (int nb = 0; nb < 2; nb++) {
                        const uint32_t* bn = reinterpret_cast<const uint32_t*>(&Bn[nb]);
                        mma16(sacc[mb][nb], a.x, a.y, a.z, a.w, bn[2*ss], bn[2*ss+1]);
                    }
                }
        }
        // relu^2 -> sS (fragment order, precomputed pointers)
#pragma unroll
        for (int mb = 0; mb < 2; mb++)
#pragma unroll
            for (int nb = 0; nb < 2; nb++) {
                float v0 = fmaxf(sacc[mb][nb][0], 0.f), v1 = fmaxf(sacc[mb][nb][1], 0.f);
                float v2 = fmaxf(sacc[mb][nb][2], 0.f), v3 = fmaxf(sacc[mb][nb][3], 0.f);
                *reinterpret_cast<uint2*>(sstore[mb][nb]) =
                    make_uint2(h2pack(v0 * v0, v1 * v1), h2pack(v2 * v2, v3 * v3));
            }
        __syncthreads();

        if (j + 2 < NJT) loadX((j + 2) * JT, xdst);

        // phase 2: Y(32x64/warp) += S @ T over K=64
#pragma unroll
        for (int kc2 = 0; kc2 < 2; kc2++) {
            uint4 Sq[2][2];
#pragma unroll
            for (int mb = 0; mb < 2; mb++)
#pragma unroll
                for (int ss = 0; ss < 2; ss++)
                    Sq[mb][ss] = sqB[(mb * 4 + kc2 * 2 + ss) * 32];
#pragma unroll
            for (int nt = 0; nt < 8; nt++) {
                uint4 Bv = ttB[8 * nt * TP + 4 * kc2];
                const uint32_t* bn = reinterpret_cast<const uint32_t*>(&Bv);
#pragma unroll
                for (int ss = 0; ss < 2; ss++)
#pragma unroll
                    for (int mb = 0; mb < 2; mb++) {
                        uint4 a = Sq[mb][ss];
                        mma16(yacc[mb][nt], a.x, a.y, a.z, a.w, bn[2*ss], bn[2*ss+1]);
                    }
            }
        }
        __syncthreads();

        if (j + 2 < NJT) { loadT((j + 2) * JT, tdst); CP_COMMIT(); }
    };

    int j = 0;
#pragma unroll 1
    for (; j + 1 < NJT; j += 2) {
        iter(j,     xjB0, ttB0, xdst0, tdst0, false);
        iter(j + 1, xjB1, ttB1, xdst1, tdst1, false);
    }
    iter(j, xjB0, ttB0, xdst0, tdst0, true);   // j = NJT-1 = 48 (even)

    // epilogue
    float* Yb = y + ((size_t)b * HW_DIM + i0) * C_DIM;
#pragma unroll
    for (int mb = 0; mb < 2; mb++) {
        int r1 = 32 * wr + 16 * mb + gid;
#pragma unroll
        for (int nt = 0; nt < 8; nt++) {
            int c = 64 * wn + 8 * nt + 2 * tig;
            *reinterpret_cast<float2*>(&Yb[(size_t)r1 * C_DIM + c]) =
                make_float2(yacc[mb][nt][0], yacc[mb][nt][1]);
            *reinterpret_cast<float2*>(&Yb[(size_t)(r1 + 8) * C_DIM + c]) =
                make_float2(yacc[mb][nt][2], yacc[mb][nt][3]);
        }
    }
}

// ---------------------------------------------------------------------------
extern "C" void kernel_launch(void* const* d_in, const int* in_sizes, int n_in,
                              void* d_out, int out_size) {
    const float* x = (const float*)d_in[0];
    const float* W = (const float*)d_in[1];
    float* y = (float*)d_out;
    (void)in_sizes; (void)n_in; (void)out_size;

    norm_kernel<<<NROWS / 8, dim3(32, 8)>>>(x);
    wt_kernel<<<C_DIM, C_DIM>>>(W);
    xa_kernel<<<NROWS / 64, 256>>>();

    cudaFuncSetAttribute(transform_mma, cudaFuncAttributeMaxDynamicSharedMemorySize, TM_TOT);
    transform_mma<<<NROWS / 64, 256, TM_TOT>>>();

    cudaFuncSetAttribute(ppm_fused, cudaFuncAttributeMaxDynamicSharedMemorySize, SM_TOT);
    ppm_fused<<<dim3(HW_DIM / JT, B_DIM), 256, SM_TOT>>>(y);
}